// round 14
// baseline (speedup 1.0000x reference)
#include <cuda_runtime.h>
#include <cstdint>

// ============================================================================
// ConvLSTMEncoder == 3-layer LSTM (K=3 conv over length-1 dim -> center tap).
//   B=256, T=512, CIN=64, H=128.  gates[b,4H] = [in; h] @ Wc^T + bias
// Round-14: crossbar-balanced fat tile. Evidence: gemv was LDS-wavefront
// bound (12 wf per 16 FMA2 -> 8448 cyc/SM vs fma floor 5632). New lane tile
// 8 rows x 8 batches: 16 wf per 32 FMA2, iters halved -> gemv crossbar
// 5632 cyc/SM == fma floor (co-bound, neither in excess).
//   Geometry: warp = rp(4 row-groups of 16) x bh(2 batch-halves);
//             lane = ro(1: 8-row block) x kc(4: 16 k-chunks).
//   kc folded 2 levels (bfly 2,4) -> 4 pbuf copies (copy = lane>>3),
//   bank-staggered via XOR swizzle (r ^ 2b ^ 2copy): store phase uses banks
//   {0,2..14} (conflict-free), cell reads conflict-free, u64-aligned.
//   pbuf [4][16][64] = 4096 floats; smem total = 232448 B (opt-in max).
// Ladder (R12 structure, proven): h-asm -> BAR -> (gemv Lx -> BAR -> cell Lx
//   -> BAR) x3 -> split cross-CTA counter barrier with x(s+1) prefetch in
//   the poll window. Padded per-group counters.
// 128 CTAs = 16 batch-groups x 8 gate-slices; weights fp32 in SMEM;
// h exchange via L2 __device__ buffer.
// ============================================================================

#define T_STEPS 512

// smem float offsets:
#define WOFF_L0 0            // 192*64 = 12288
#define WOFF_L1 12288        // 256*64 = 16384
#define WOFF_L2 28672        // 16384
#define ZD_OFF  45056        // z: [448][20] floats = 8960
#define PB_OFF  54016        // pbuf: [4][16][64] swizzled = 4096
#define SMEM_FLOATS 58112
#define SMEM_BYTES  (SMEM_FLOATS * 4)   // 232448 == opt-in max

__device__ float    g_hbuf[3 * 2 * 128 * 256];  // [layer][parity][unit][batch]
__device__ unsigned g_ctr[16 * 32];             // padded: one counter / 128B

__global__ void reset_ctr_kernel() {
    if (threadIdx.x < 16) g_ctr[threadIdx.x * 32] = 0u;
}

__device__ __forceinline__ float fast_rcp(float x) {
    float r; asm("rcp.approx.f32 %0, %1;" : "=f"(r) : "f"(x)); return r;
}
__device__ __forceinline__ float sigm(float x) {
    return fast_rcp(1.0f + __expf(-x));
}
__device__ __forceinline__ float tanh_f(float x) {
    x = fminf(fmaxf(x, -15.0f), 15.0f);
    float e = __expf(-2.0f * x);
    return (1.0f - e) * fast_rcp(1.0f + e);
}

#define FMA2(acc, a, b) asm("fma.rn.f32x2 %0, %1, %2, %0;" : "+l"(acc) : "l"(a), "l"(b))
#define DUP2(d, s)      asm("mov.b64 %0, {%1, %1};" : "=l"(d) : "r"(__float_as_uint(s)))

// butterfly reduce of an f32x2 pair across lanes (xor mask)
__device__ __forceinline__ unsigned long long bfly_add2(unsigned long long a, int m) {
    unsigned lo = (unsigned)a, hi = (unsigned)(a >> 32);
    unsigned plo = __shfl_xor_sync(0xffffffffu, lo, m);
    unsigned phi = __shfl_xor_sync(0xffffffffu, hi, m);
    unsigned long long p = ((unsigned long long)phi << 32) | plo;
    unsigned long long r;
    asm("add.rn.f32x2 %0, %1, %2;" : "=l"(r) : "l"(a), "l"(p));
    return r;
}

// GEMV for one layer: lane tile 8 rows x 8 batches over its k-chunk (KD/16).
// kc low 2 bits folded (bfly 2,4); lanes with (lane&6)==0 store copy lane>>3.
template<int KD>
__device__ __forceinline__ void gemv_layer(
    const float* __restrict__ Wbase,   // Wsm + layer offset
    const float* __restrict__ zbase,   // zdf + zrow0*20
    int kc, int r0, int b0, int lane, float* __restrict__ pbuf)
{
    constexpr int C = KD / 16;         // iters per lane (12 / 16)
    const float* Wcol = Wbase + kc * (C * 64) + r0;
    const float* zcol = zbase + kc * (C * 20) + b0;

    unsigned long long acc[4][8];
#pragma unroll
    for (int i = 0; i < 4; i++)
#pragma unroll
        for (int j = 0; j < 8; j++) acc[i][j] = 0ULL;

#pragma unroll 4
    for (int k = 0; k < C; k++) {
        ulonglong2 wa = *(const ulonglong2*)(Wcol + k * 64);      // rows r0..r0+3
        ulonglong2 wb = *(const ulonglong2*)(Wcol + k * 64 + 4);  // rows r0+4..r0+7
        float4 za = *(const float4*)(zcol + k * 20);              // batches b0..b0+3
        float4 zb4 = *(const float4*)(zcol + k * 20 + 4);         // batches b0+4..b0+7
        unsigned long long zz[8];
        DUP2(zz[0], za.x);  DUP2(zz[1], za.y);
        DUP2(zz[2], za.z);  DUP2(zz[3], za.w);
        DUP2(zz[4], zb4.x); DUP2(zz[5], zb4.y);
        DUP2(zz[6], zb4.z); DUP2(zz[7], zb4.w);
#pragma unroll
        for (int j = 0; j < 8; j++) {
            FMA2(acc[0][j], wa.x, zz[j]);
            FMA2(acc[1][j], wa.y, zz[j]);
            FMA2(acc[2][j], wb.x, zz[j]);
            FMA2(acc[3][j], wb.y, zz[j]);
        }
    }
    // fold kc low bits (lane bits 1,2): chunks 4c..4c+3 summed per group
#pragma unroll
    for (int i = 0; i < 4; i++)
#pragma unroll
        for (int j = 0; j < 8; j++)
            acc[i][j] = bfly_add2(bfly_add2(acc[i][j], 2), 4);

    if ((lane & 6) == 0) {             // holders: ro x copy(lane>>3)
        const int cp = lane >> 3;
        float* pd = pbuf + cp * 1024;
        const int swc = 2 * cp;
#pragma unroll
        for (int j = 0; j < 8; j++) {
            const int b = b0 + j;
            float* col = pd + b * 64;
            const int sw = (2 * b) ^ swc;
#pragma unroll
            for (int i = 0; i < 4; i++)
                *(unsigned long long*)(col + ((r0 + 2 * i) ^ sw)) = acc[i][j];
        }
    }
}

// cell phase helper: gate sums over the 4 pbuf copies (swizzled reads)
__device__ __forceinline__ float4 gate_sums(const float* __restrict__ pbuf,
                                            int u, int b, float4 bL)
{
    float gi = bL.x, gf = bL.y, go = bL.z, gg = bL.w;
#pragma unroll
    for (int cp = 0; cp < 4; cp++) {
        const float* gb = pbuf + cp * 1024 + b * 64;
        const int sw = (2 * b) ^ (2 * cp);
        gi += gb[u ^ sw];
        gf += gb[(16 + u) ^ sw];
        go += gb[(32 + u) ^ sw];
        gg += gb[(48 + u) ^ sw];
    }
    return make_float4(gi, gf, go, gg);
}

__global__ void __launch_bounds__(256, 1) convlstm_kernel(
    const float* __restrict__ x,
    const float* __restrict__ W1, const float* __restrict__ b1,
    const float* __restrict__ W2, const float* __restrict__ b2,
    const float* __restrict__ W3, const float* __restrict__ b3,
    const float* __restrict__ h1i, const float* __restrict__ c1i,
    const float* __restrict__ h2i, const float* __restrict__ c2i,
    const float* __restrict__ h3i, const float* __restrict__ c3i,
    float* __restrict__ out)
{
    extern __shared__ float sm[];
    float* Wsm  = sm;
    float* zdf  = sm + ZD_OFF;
    float* pbuf = sm + PB_OFF;

    const int tid = threadIdx.x;
    const int gid = blockIdx.x & 7;    // gate-slice: hidden units [16*gid, +16)
    const int bg  = blockIdx.x >> 3;   // batch group: batches [16*bg, +16)
    const int bgb = bg << 4;
    unsigned* ctr = &g_ctr[bg * 32];

    // ---- Prologue: weight slices (center tap), plain [k][row64] ----
    for (int idx = tid; idx < 192 * 64; idx += 256) {
        int k = idx >> 6, r = idx & 63;
        int grow = ((r >> 4) << 7) | (gid << 4) | (r & 15);  // gate*128+gid*16+u
        Wsm[WOFF_L0 + idx] = W1[(size_t)grow * 576 + k * 3 + 1];
    }
    for (int idx = tid; idx < 256 * 64; idx += 256) {
        int k = idx >> 6, r = idx & 63;
        int grow = ((r >> 4) << 7) | (gid << 4) | (r & 15);
        Wsm[WOFF_L1 + idx] = W2[(size_t)grow * 768 + k * 3 + 1];
        Wsm[WOFF_L2 + idx] = W3[(size_t)grow * 768 + k * 3 + 1];
    }

    // ---- per-thread (u,b) registers: bias + c state ----
    const int u = tid >> 4, b = tid & 15;
    const int gub = (gid << 4) | u;
    float4 bL0 = make_float4(__ldg(&b1[gub]), __ldg(&b1[128 + gub]),
                             __ldg(&b1[256 + gub]), __ldg(&b1[384 + gub]));
    float4 bL1 = make_float4(__ldg(&b2[gub]), __ldg(&b2[128 + gub]),
                             __ldg(&b2[256 + gub]), __ldg(&b2[384 + gub]));
    float4 bL2 = make_float4(__ldg(&b3[gub]), __ldg(&b3[128 + gub]),
                             __ldg(&b3[256 + gub]), __ldg(&b3[384 + gub]));
    const int sidx = (bgb + b) * 128 + gub;
    float c0r = __ldg(&c1i[sidx]);
    float c1r = __ldg(&c2i[sidx]);
    float c2r = __ldg(&c3i[sidx]);

    // ---- publish initial h into both parities ----
    {
        float h0 = __ldg(&h1i[sidx]), h1v = __ldg(&h2i[sidx]), h2v = __ldg(&h3i[sidx]);
        int hb = gub * 256 + bgb + b;
#pragma unroll
        for (int par = 0; par < 2; par++) {
            g_hbuf[(0 * 2 + par) * 32768 + hb] = h0;
            g_hbuf[(1 * 2 + par) * 32768 + hb] = h1v;
            g_hbuf[(2 * 2 + par) * 32768 + hb] = h2v;
        }
    }
    // initial cross-CTA barrier
    unsigned target = 8;
    __syncthreads();
    if (tid == 0) {
        __threadfence();
        atomicAdd(ctr, 1u);
        unsigned v;
        do {
            asm volatile("ld.global.acquire.gpu.u32 %0, [%1];"
                         : "=r"(v) : "l"(ctr) : "memory");
            if (v < target) __nanosleep(20);
        } while (v < target);
    }
    target += 8;
    __syncthreads();

    // ---- initial x(0) assembly ----
    {
        const float* xb = x + (size_t)bgb * (T_STEPS * 64);
        int bb = tid >> 4, k4i = (tid & 15) << 2;
        float4 v = __ldg((const float4*)(xb + (size_t)bb * (T_STEPS * 64) + k4i));
        zdf[(k4i + 0) * 20 + bb] = v.x;
        zdf[(k4i + 1) * 20 + bb] = v.y;
        zdf[(k4i + 2) * 20 + bb] = v.z;
        zdf[(k4i + 3) * 20 + bb] = v.w;
    }

    // GEMV warp/lane geometry: warp = rp(4) x bh(2); lane = ro(bit0) x kc(bits1-4)
    const int warp = tid >> 5, lane = tid & 31;
    const int rp = warp & 3;             // 16-row group
    const int bh = warp >> 2;            // 8-batch half
    const int ro = lane & 1;             // 8-row block within group
    const int kc = lane >> 1;            // k-chunk 0..15 (low 2 bits folded)
    const int r0 = rp * 16 + ro * 8;     // rows r0..r0+7
    const int b0 = bh * 8;               // batches b0..b0+7

    // ======================= macro-step pipeline =======================
    for (int s = 0; s < T_STEPS + 2; s++) {
        const int pc = s & 1, pp = pc ^ 1;

        // ---- h-assembly: z rows 64..447 (x written in prior poll window) ----
#pragma unroll
        for (int Lh = 0; Lh < 3; Lh++) {
            const float* src = &g_hbuf[(Lh * 2 + pp) * 32768 + bgb];
#pragma unroll
            for (int i = 0; i < 2; i++) {
                int idx = tid + (i << 8);
                int unit = idx >> 2, b4 = (idx & 3) << 2;
                float4 v = __ldcg((const float4*)&src[unit * 256 + b4]);
                *(float4*)&zdf[(64 + (Lh << 7) + unit) * 20 + b4] = v;
            }
        }
        __syncthreads();

        // -------- L0: t = s  (z rows 0..191) --------
        if (s < T_STEPS)
            gemv_layer<192>(Wsm + WOFF_L0, zdf, kc, r0, b0, lane, pbuf);
        __syncthreads();
        if (s < T_STEPS) {
            float4 g = gate_sums(pbuf, u, b, bL0);
            float cn = sigm(g.y) * c0r + sigm(g.x) * tanh_f(g.w);
            float hn = sigm(g.z) * tanh_f(cn);
            c0r = cn;
            g_hbuf[(0 * 2 + pc) * 32768 + gub * 256 + bgb + b] = hn;
        }
        __syncthreads();

        // -------- L1: t = s-1  (z rows 64..319) --------
        if (s >= 1 && s <= T_STEPS)
            gemv_layer<256>(Wsm + WOFF_L1, zdf + 64 * 20, kc, r0, b0, lane, pbuf);
        __syncthreads();
        if (s >= 1 && s <= T_STEPS) {
            float4 g = gate_sums(pbuf, u, b, bL1);
            float cn = sigm(g.y) * c1r + sigm(g.x) * tanh_f(g.w);
            float hn = sigm(g.z) * tanh_f(cn);
            c1r = cn;
            g_hbuf[(1 * 2 + pc) * 32768 + gub * 256 + bgb + b] = hn;
        }
        __syncthreads();

        // -------- L2: t = s-2  (z rows 192..447) --------
        if (s >= 2)
            gemv_layer<256>(Wsm + WOFF_L2, zdf + 192 * 20, kc, r0, b0, lane, pbuf);
        __syncthreads();
        if (s >= 2) {
            float4 g = gate_sums(pbuf, u, b, bL2);
            float cn = sigm(g.y) * c2r + sigm(g.x) * tanh_f(g.w);
            float hn = sigm(g.z) * tanh_f(cn);
            c2r = cn;
            g_hbuf[(2 * 2 + pc) * 32768 + gub * 256 + bgb + b] = hn;
            if (s == T_STEPS + 1)
                out[(size_t)(bgb + b) * 128 + gub] = hn;
        }

        // ---- split cross-CTA barrier; x(s+1) assembly overlaps the poll ----
        __syncthreads();
        if (tid == 0) {
            __threadfence();
            atomicAdd(ctr, 1u);
        }
        if (s + 1 < T_STEPS) {
            const float* xb = x + (size_t)bgb * (T_STEPS * 64) + (size_t)(s + 1) * 64;
            int bb = tid >> 4, k4i = (tid & 15) << 2;
            float4 v = __ldg((const float4*)(xb + (size_t)bb * (T_STEPS * 64) + k4i));
            zdf[(k4i + 0) * 20 + bb] = v.x;
            zdf[(k4i + 1) * 20 + bb] = v.y;
            zdf[(k4i + 2) * 20 + bb] = v.z;
            zdf[(k4i + 3) * 20 + bb] = v.w;
        }
        if (tid == 0) {
            unsigned v;
            do {
                asm volatile("ld.global.acquire.gpu.u32 %0, [%1];"
                             : "=r"(v) : "l"(ctr) : "memory");
                if (v < target) __nanosleep(20);
            } while (v < target);
        }
        target += 8;
        __syncthreads();
    }
}

extern "C" void kernel_launch(void* const* d_in, const int* in_sizes, int n_in,
                              void* d_out, int out_size) {
    (void)in_sizes; (void)n_in; (void)out_size;
    const float* x  = (const float*)d_in[0];
    const float* W1 = (const float*)d_in[1];
    const float* b1 = (const float*)d_in[2];
    const float* W2 = (const float*)d_in[3];
    const float* b2 = (const float*)d_in[4];
    const float* W3 = (const float*)d_in[5];
    const float* b3 = (const float*)d_in[6];
    const float* h1 = (const float*)d_in[7];
    const float* c1 = (const float*)d_in[8];
    const float* h2 = (const float*)d_in[9];
    const float* c2 = (const float*)d_in[10];
    const float* h3 = (const float*)d_in[11];
    const float* c3 = (const float*)d_in[12];
    float* out = (float*)d_out;

    cudaFuncSetAttribute(convlstm_kernel,
                         cudaFuncAttributeMaxDynamicSharedMemorySize, SMEM_BYTES);
    reset_ctr_kernel<<<1, 32>>>();
    convlstm_kernel<<<128, 256, SMEM_BYTES>>>(x, W1, b1, W2, b2, W3, b3,
                                              h1, c1, h2, c2, h3, c3, out);
}

// round 15
// speedup vs baseline: 1.9339x; 1.9339x over previous
#include <cuda_runtime.h>
#include <cstdint>

// ============================================================================
// ConvLSTMEncoder == 3-layer LSTM (K=3 conv over length-1 dim -> center tap).
//   B=256, T=512, CIN=64, H=128.  gates[b,4H] = [in; h] @ Wc^T + bias
// Round-15: R13 (best, 4286us) + h0-latency hiding via split gemv L0.
//   R13 phase A exposed the h0 __ldcg latency (~600cyc) with no overlap.
//   Fix: gemv L0 accumulates in two segments over the same registers:
//     seg1: x rows   (chunk kc -> rows kc*8..+8)    -- runs while h loads fly
//     seg2: h0 rows  (chunk kc -> rows 64+kc*16..+16) -- after h0 stored, BAR
//   No layout changes; W/z/pbuf/barriers identical to R13.
//   Phases: A: issue h0/h1/h2 LDGs, gemv L0 seg1, STS h0            -> BAR
//           B: gemv L0 seg2 + fold -> set0, STS h1/h2               -> BAR
//           C: gemv L1 -> set1; cell L0 (set0)                      -> BAR
//           D: gemv L2 -> set0; cell L1 (set1)                      -> BAR
//           E: cell L2; publish; group barrier (x(s+1) in poll window)
// R14 lesson recorded: fat tiles beyond acc=32 regs (8rx4b) hit register
//   pressure (218 regs) and collapse; do not revisit.
// 128 CTAs = 16 batch-groups x 8 gate-slices; weights fp32 in SMEM;
// h exchange via L2 __device__ buffer + padded monotonic counter barrier.
// ============================================================================

#define T_STEPS 512

// smem float offsets:
#define WOFF_L0 0            // 192*64 = 12288
#define WOFF_L1 12288        // 256*64 = 16384
#define WOFF_L2 28672        // 16384
#define ZD_OFF  45056        // z: [448][20] floats = 8960
#define PB_OFF  54016        // pbuf: [2 sets][2 copies][16][64] = 4096
#define SMEM_FLOATS 58112
#define SMEM_BYTES  (SMEM_FLOATS * 4)   // 232448 (opt-in max)

__device__ float    g_hbuf[3 * 2 * 128 * 256];  // [layer][parity][unit][batch]
__device__ unsigned g_ctr[16 * 32];             // padded: one counter / 128B

__global__ void reset_ctr_kernel() {
    if (threadIdx.x < 16) g_ctr[threadIdx.x * 32] = 0u;
}

__device__ __forceinline__ float fast_rcp(float x) {
    float r; asm("rcp.approx.f32 %0, %1;" : "=f"(r) : "f"(x)); return r;
}
__device__ __forceinline__ float sigm(float x) {
    return fast_rcp(1.0f + __expf(-x));
}
__device__ __forceinline__ float tanh_f(float x) {
    x = fminf(fmaxf(x, -15.0f), 15.0f);
    float e = __expf(-2.0f * x);
    return (1.0f - e) * fast_rcp(1.0f + e);
}

#define FMA2(acc, a, b) asm("fma.rn.f32x2 %0, %1, %2, %0;" : "+l"(acc) : "l"(a), "l"(b))
#define DUP2(d, s)      asm("mov.b64 %0, {%1, %1};" : "=l"(d) : "r"(__float_as_uint(s)))

// butterfly reduce of an f32x2 pair across lanes (xor mask)
__device__ __forceinline__ unsigned long long bfly_add2(unsigned long long a, int m) {
    unsigned lo = (unsigned)a, hi = (unsigned)(a >> 32);
    unsigned plo = __shfl_xor_sync(0xffffffffu, lo, m);
    unsigned phi = __shfl_xor_sync(0xffffffffu, hi, m);
    unsigned long long p = ((unsigned long long)phi << 32) | plo;
    unsigned long long r;
    asm("add.rn.f32x2 %0, %1, %2;" : "=l"(r) : "l"(a), "l"(p));
    return r;
}

// accumulate ITERS k-steps into acc (lane tile 8 rows x 4 batches)
template<int ITERS>
__device__ __forceinline__ void gemv_accum(
    const float* __restrict__ Wcol, const float* __restrict__ zcol,
    unsigned long long acc[4][4])
{
#pragma unroll 4
    for (int k = 0; k < ITERS; k++) {
        ulonglong2 wa = *(const ulonglong2*)(Wcol + k * 64);      // rows r0..r0+3
        ulonglong2 wb = *(const ulonglong2*)(Wcol + k * 64 + 4);  // rows r0+4..r0+7
        float4 z4 = *(const float4*)(zcol + k * 20);              // batches b0..b0+3
        unsigned long long zz[4];
        DUP2(zz[0], z4.x); DUP2(zz[1], z4.y);
        DUP2(zz[2], z4.z); DUP2(zz[3], z4.w);
#pragma unroll
        for (int j = 0; j < 4; j++) {
            FMA2(acc[0][j], wa.x, zz[j]);
            FMA2(acc[1][j], wa.y, zz[j]);
            FMA2(acc[2][j], wb.x, zz[j]);
            FMA2(acc[3][j], wb.y, zz[j]);
        }
    }
}

// fold lane bits 3,4 and store copy kq of a pbuf set (swizzled, lanes 0..7)
__device__ __forceinline__ void gemv_fold_store(
    unsigned long long acc[4][4], int kq, int r0, int b0, int lane,
    float* __restrict__ pset)
{
#pragma unroll
    for (int i = 0; i < 4; i++)
#pragma unroll
        for (int j = 0; j < 4; j++)
            acc[i][j] = bfly_add2(bfly_add2(acc[i][j], 8), 16);
    if (lane < 8) {
        float* pd = pset + kq * 1024;
#pragma unroll
        for (int j = 0; j < 4; j++) {
            const int b = b0 + j;
            float* col = pd + b * 64;
            const int sw = 2 * b;
#pragma unroll
            for (int i = 0; i < 4; i++)
                *(unsigned long long*)(col + ((r0 + 2 * i) ^ sw)) = acc[i][j];
        }
    }
}

// single-call gemv (L1/L2): contiguous chunk of KD/8 k-steps
template<int KD>
__device__ __forceinline__ void gemv_layer(
    const float* __restrict__ Wbase, const float* __restrict__ zbase,
    int kc, int kq, int r0, int b0, int lane, float* __restrict__ pset)
{
    constexpr int C = KD / 8;
    unsigned long long acc[4][4];
#pragma unroll
    for (int i = 0; i < 4; i++)
#pragma unroll
        for (int j = 0; j < 4; j++) acc[i][j] = 0ULL;
    gemv_accum<C>(Wbase + kc * (C * 64) + r0, zbase + kc * (C * 20) + b0, acc);
    gemv_fold_store(acc, kq, r0, b0, lane, pset);
}

// cell phase helper: gate sums from a pbuf set (2 copies), swizzled reads
__device__ __forceinline__ float4 gate_sums(const float* __restrict__ pset,
                                            int u, int b, float4 bL)
{
    const int sw = 2 * b;
    float gi = bL.x, gf = bL.y, go = bL.z, gg = bL.w;
#pragma unroll
    for (int c = 0; c < 2; c++) {
        const float* gb = pset + c * 1024 + b * 64;
        gi += gb[u ^ sw];
        gf += gb[(16 + u) ^ sw];
        go += gb[(32 + u) ^ sw];
        gg += gb[(48 + u) ^ sw];
    }
    return make_float4(gi, gf, go, gg);
}

__global__ void __launch_bounds__(256, 1) convlstm_kernel(
    const float* __restrict__ x,
    const float* __restrict__ W1, const float* __restrict__ b1,
    const float* __restrict__ W2, const float* __restrict__ b2,
    const float* __restrict__ W3, const float* __restrict__ b3,
    const float* __restrict__ h1i, const float* __restrict__ c1i,
    const float* __restrict__ h2i, const float* __restrict__ c2i,
    const float* __restrict__ h3i, const float* __restrict__ c3i,
    float* __restrict__ out)
{
    extern __shared__ float sm[];
    float* Wsm  = sm;
    float* zdf  = sm + ZD_OFF;
    float* pbuf = sm + PB_OFF;

    const int tid = threadIdx.x;
    const int gid = blockIdx.x & 7;    // gate-slice: hidden units [16*gid, +16)
    const int bg  = blockIdx.x >> 3;   // batch group: batches [16*bg, +16)
    const int bgb = bg << 4;
    unsigned* ctr = &g_ctr[bg * 32];

    // ---- Prologue: weight slices (center tap), plain [k][row64] ----
    for (int idx = tid; idx < 192 * 64; idx += 256) {
        int k = idx >> 6, r = idx & 63;
        int grow = ((r >> 4) << 7) | (gid << 4) | (r & 15);  // gate*128+gid*16+u
        Wsm[WOFF_L0 + idx] = W1[(size_t)grow * 576 + k * 3 + 1];
    }
    for (int idx = tid; idx < 256 * 64; idx += 256) {
        int k = idx >> 6, r = idx & 63;
        int grow = ((r >> 4) << 7) | (gid << 4) | (r & 15);
        Wsm[WOFF_L1 + idx] = W2[(size_t)grow * 768 + k * 3 + 1];
        Wsm[WOFF_L2 + idx] = W3[(size_t)grow * 768 + k * 3 + 1];
    }

    // ---- per-thread (u,b) registers: bias + c state ----
    const int u = tid >> 4, b = tid & 15;
    const int gub = (gid << 4) | u;
    float4 bL0 = make_float4(__ldg(&b1[gub]), __ldg(&b1[128 + gub]),
                             __ldg(&b1[256 + gub]), __ldg(&b1[384 + gub]));
    float4 bL1 = make_float4(__ldg(&b2[gub]), __ldg(&b2[128 + gub]),
                             __ldg(&b2[256 + gub]), __ldg(&b2[384 + gub]));
    float4 bL2 = make_float4(__ldg(&b3[gub]), __ldg(&b3[128 + gub]),
                             __ldg(&b3[256 + gub]), __ldg(&b3[384 + gub]));
    const int sidx = (bgb + b) * 128 + gub;
    float c0r = __ldg(&c1i[sidx]);
    float c1r = __ldg(&c2i[sidx]);
    float c2r = __ldg(&c3i[sidx]);

    // ---- publish initial h into both parities ----
    {
        float h0 = __ldg(&h1i[sidx]), h1v = __ldg(&h2i[sidx]), h2v = __ldg(&h3i[sidx]);
        int hb = gub * 256 + bgb + b;
#pragma unroll
        for (int par = 0; par < 2; par++) {
            g_hbuf[(0 * 2 + par) * 32768 + hb] = h0;
            g_hbuf[(1 * 2 + par) * 32768 + hb] = h1v;
            g_hbuf[(2 * 2 + par) * 32768 + hb] = h2v;
        }
    }
    // initial cross-CTA barrier
    unsigned target = 8;
    __syncthreads();
    if (tid == 0) {
        __threadfence();
        atomicAdd(ctr, 1u);
        unsigned v;
        do {
            asm volatile("ld.global.acquire.gpu.u32 %0, [%1];"
                         : "=r"(v) : "l"(ctr) : "memory");
            if (v < target) __nanosleep(20);
        } while (v < target);
    }
    target += 8;
    __syncthreads();

    // ---- initial x(0) assembly (z rows 0..63) ----
    {
        const float* xb = x + (size_t)bgb * (T_STEPS * 64);
        int bb = tid >> 4, k4i = (tid & 15) << 2;
        float4 v = __ldg((const float4*)(xb + (size_t)bb * (T_STEPS * 64) + k4i));
        zdf[(k4i + 0) * 20 + bb] = v.x;
        zdf[(k4i + 1) * 20 + bb] = v.y;
        zdf[(k4i + 2) * 20 + bb] = v.z;
        zdf[(k4i + 3) * 20 + bb] = v.w;
    }
    __syncthreads();

    // GEMV warp/lane geometry (R13/R10)
    const int warp = tid >> 5, lane = tid & 31;
    const int kq = warp & 1;             // k-half (pbuf copy)
    const int rh = (warp >> 1) & 1;      // 32-row half
    const int bh = warp >> 2;            // 8-batch half
    const int ro = lane & 3;             // 8-row block within half
    const int bp = (lane >> 2) & 1;      // 4-batch within half
    const int kl = lane >> 3;            // in-lane k-chunk bits (folded)
    const int kc = kq * 4 + kl;          // k-chunk 0..7
    const int r0 = rh * 32 + ro * 8;     // rows r0..r0+7
    const int b0 = bh * 8 + bp * 4;      // batches b0..b0+3

    // h-assembly thread indexing
    const int aunit = tid >> 2;          // 0..63 (x2 with +64)
    const int ab4   = (tid & 3) << 2;

    // ======================= macro-step pipeline =======================
    for (int s = 0; s < T_STEPS + 2; s++) {
        const int pc = s & 1, pp = pc ^ 1;

        // ---- phase A: issue ALL h loads; gemv L0 seg1 (x rows); STS h0 ----
        float4 hv[6];
#pragma unroll
        for (int Lh = 0; Lh < 3; Lh++) {
            const float* src = &g_hbuf[(Lh * 2 + pp) * 32768 + bgb];
#pragma unroll
            for (int i = 0; i < 2; i++) {
                int unit = aunit + (i << 6);
                hv[Lh * 2 + i] = __ldcg((const float4*)&src[unit * 256 + ab4]);
            }
        }
        unsigned long long acc0[4][4];
#pragma unroll
        for (int i = 0; i < 4; i++)
#pragma unroll
            for (int j = 0; j < 4; j++) acc0[i][j] = 0ULL;
        if (s < T_STEPS)   // seg1: x rows kc*8..kc*8+8 (in smem since poll window)
            gemv_accum<8>(Wsm + WOFF_L0 + (kc * 8) * 64 + r0,
                          zdf + (kc * 8) * 20 + b0, acc0);
#pragma unroll
        for (int i = 0; i < 2; i++) {     // store h0 -> z rows 64..191
            int unit = aunit + (i << 6);
            *(float4*)&zdf[(64 + unit) * 20 + ab4] = hv[i];
        }
        __syncthreads();

        // ---- phase B: gemv L0 seg2 (h0 rows) -> set0; STS h1/h2 ----
        if (s < T_STEPS) {
            gemv_accum<16>(Wsm + WOFF_L0 + (64 + kc * 16) * 64 + r0,
                           zdf + (64 + kc * 16) * 20 + b0, acc0);
            gemv_fold_store(acc0, kq, r0, b0, lane, pbuf);
        }
#pragma unroll
        for (int Lh = 1; Lh <= 2; Lh++) {
#pragma unroll
            for (int i = 0; i < 2; i++) {
                int unit = aunit + (i << 6);
                *(float4*)&zdf[(64 + (Lh << 7) + unit) * 20 + ab4] = hv[Lh * 2 + i];
            }
        }
        __syncthreads();

        // ---- phase C: gemv L1 -> set1; cell L0 (reads set0) ----
        if (s >= 1 && s <= T_STEPS)
            gemv_layer<256>(Wsm + WOFF_L1, zdf + 64 * 20, kc, kq, r0, b0, lane,
                            pbuf + 2048);
        if (s < T_STEPS) {
            float4 g = gate_sums(pbuf, u, b, bL0);
            float cn = sigm(g.y) * c0r + sigm(g.x) * tanh_f(g.w);
            float hn = sigm(g.z) * tanh_f(cn);
            c0r = cn;
            g_hbuf[(0 * 2 + pc) * 32768 + gub * 256 + bgb + b] = hn;
        }
        __syncthreads();

        // ---- phase D: gemv L2 -> set0; cell L1 (reads set1) ----
        if (s >= 2)
            gemv_layer<256>(Wsm + WOFF_L2, zdf + 192 * 20, kc, kq, r0, b0, lane,
                            pbuf);
        if (s >= 1 && s <= T_STEPS) {
            float4 g = gate_sums(pbuf + 2048, u, b, bL1);
            float cn = sigm(g.y) * c1r + sigm(g.x) * tanh_f(g.w);
            float hn = sigm(g.z) * tanh_f(cn);
            c1r = cn;
            g_hbuf[(1 * 2 + pc) * 32768 + gub * 256 + bgb + b] = hn;
        }
        __syncthreads();

        // ---- phase E: cell L2 (reads set0) ----
        if (s >= 2) {
            float4 g = gate_sums(pbuf, u, b, bL2);
            float cn = sigm(g.y) * c2r + sigm(g.x) * tanh_f(g.w);
            float hn = sigm(g.z) * tanh_f(cn);
            c2r = cn;
            g_hbuf[(2 * 2 + pc) * 32768 + gub * 256 + bgb + b] = hn;
            if (s == T_STEPS + 1)
                out[(size_t)(bgb + b) * 128 + gub] = hn;
        }

        // ---- split cross-CTA barrier; x(s+1) assembly overlaps the poll ----
        __syncthreads();
        if (tid == 0) {
            __threadfence();
            atomicAdd(ctr, 1u);
        }
        if (s + 1 < T_STEPS) {
            const float* xb = x + (size_t)bgb * (T_STEPS * 64) + (size_t)(s + 1) * 64;
            int bb = tid >> 4, k4i = (tid & 15) << 2;
            float4 v = __ldg((const float4*)(xb + (size_t)bb * (T_STEPS * 64) + k4i));
            zdf[(k4i + 0) * 20 + bb] = v.x;
            zdf[(k4i + 1) * 20 + bb] = v.y;
            zdf[(k4i + 2) * 20 + bb] = v.z;
            zdf[(k4i + 3) * 20 + bb] = v.w;
        }
        if (tid == 0) {
            unsigned v;
            do {
                asm volatile("ld.global.acquire.gpu.u32 %0, [%1];"
                             : "=r"(v) : "l"(ctr) : "memory");
                if (v < target) __nanosleep(20);
            } while (v < target);
        }
        target += 8;
        __syncthreads();
    }
}

extern "C" void kernel_launch(void* const* d_in, const int* in_sizes, int n_in,
                              void* d_out, int out_size) {
    (void)in_sizes; (void)n_in; (void)out_size;
    const float* x  = (const float*)d_in[0];
    const float* W1 = (const float*)d_in[1];
    const float* b1 = (const float*)d_in[2];
    const float* W2 = (const float*)d_in[3];
    const float* b2 = (const float*)d_in[4];
    const float* W3 = (const float*)d_in[5];
    const float* b3 = (const float*)d_in[6];
    const float* h1 = (const float*)d_in[7];
    const float* c1 = (const float*)d_in[8];
    const float* h2 = (const float*)d_in[9];
    const float* c2 = (const float*)d_in[10];
    const float* h3 = (const float*)d_in[11];
    const float* c3 = (const float*)d_in[12];
    float* out = (float*)d_out;

    cudaFuncSetAttribute(convlstm_kernel,
                         cudaFuncAttributeMaxDynamicSharedMemorySize, SMEM_BYTES);
    reset_ctr_kernel<<<1, 32>>>();
    convlstm_kernel<<<128, 256, SMEM_BYTES>>>(x, W1, b1, W2, b2, W3, b3,
                                              h1, c1, h2, c2, h3, c3, out);
}

// round 16
// speedup vs baseline: 1.9690x; 1.0182x over previous
#include <cuda_runtime.h>
#include <cstdint>

// ============================================================================
// ConvLSTMEncoder == 3-layer LSTM (K=3 conv over length-1 dim -> center tap).
//   B=256, T=512, CIN=64, H=128.  gates[b,4H] = [in; h] @ Wc^T + bias
// Round-16: R15 (best, 4275us) + exposed-tail micro-cuts:
//   (a) red.release.gpu.add replaces fence+atomicAdd (grid-sync pattern:
//       syncthreads + tid0 release covers peers' writes; saves a MEMBAR)
//   (b) phases C/D run the CELL before the gemv (disjoint pbuf sets) so the
//       cell's dependency chain + h publish drain under the gemv stream
//   (c) phase B stores h1/h2 before gemv seg2 (store queue drains under it)
// Architecture notes (proven this session):
//   - 8-way gate-slice partitioning is forced by smem (full W = 1.75MB);
//     batch-pure CTAs are impossible -> cross-CTA h exchange is structural.
//   - fp32 gemv tile floor: 3 LDS per 16 FMA2 at the 32-u64 register cap.
//   - Phases: A: issue h LDGs, gemv L0 seg1 (x rows), STS h0       -> BAR
//             B: STS h1/h2, gemv L0 seg2 -> set0                   -> BAR
//             C: cell L0 (set0), gemv L1 -> set1                   -> BAR
//             D: cell L1 (set1), gemv L2 -> set0                   -> BAR
//             E: cell L2 (set0); publish; group barrier (x(s+1) prefetch
//                overlaps the poll window)
// 128 CTAs = 16 batch-groups x 8 gate-slices; weights fp32 in SMEM;
// h exchange via L2 __device__ buffer + padded monotonic counter barrier.
// ============================================================================

#define T_STEPS 512

// smem float offsets:
#define WOFF_L0 0            // 192*64 = 12288
#define WOFF_L1 12288        // 256*64 = 16384
#define WOFF_L2 28672        // 16384
#define ZD_OFF  45056        // z: [448][20] floats = 8960
#define PB_OFF  54016        // pbuf: [2 sets][2 copies][16][64] = 4096
#define SMEM_FLOATS 58112
#define SMEM_BYTES  (SMEM_FLOATS * 4)   // 232448 (opt-in max)

__device__ float    g_hbuf[3 * 2 * 128 * 256];  // [layer][parity][unit][batch]
__device__ unsigned g_ctr[16 * 32];             // padded: one counter / 128B

__global__ void reset_ctr_kernel() {
    if (threadIdx.x < 16) g_ctr[threadIdx.x * 32] = 0u;
}

__device__ __forceinline__ float fast_rcp(float x) {
    float r; asm("rcp.approx.f32 %0, %1;" : "=f"(r) : "f"(x)); return r;
}
__device__ __forceinline__ float sigm(float x) {
    return fast_rcp(1.0f + __expf(-x));
}
__device__ __forceinline__ float tanh_f(float x) {
    x = fminf(fmaxf(x, -15.0f), 15.0f);
    float e = __expf(-2.0f * x);
    return (1.0f - e) * fast_rcp(1.0f + e);
}

#define FMA2(acc, a, b) asm("fma.rn.f32x2 %0, %1, %2, %0;" : "+l"(acc) : "l"(a), "l"(b))
#define DUP2(d, s)      asm("mov.b64 %0, {%1, %1};" : "=l"(d) : "r"(__float_as_uint(s)))

// butterfly reduce of an f32x2 pair across lanes (xor mask)
__device__ __forceinline__ unsigned long long bfly_add2(unsigned long long a, int m) {
    unsigned lo = (unsigned)a, hi = (unsigned)(a >> 32);
    unsigned plo = __shfl_xor_sync(0xffffffffu, lo, m);
    unsigned phi = __shfl_xor_sync(0xffffffffu, hi, m);
    unsigned long long p = ((unsigned long long)phi << 32) | plo;
    unsigned long long r;
    asm("add.rn.f32x2 %0, %1, %2;" : "=l"(r) : "l"(a), "l"(p));
    return r;
}

// release-arrive on the group counter (caller must be past a __syncthreads)
__device__ __forceinline__ void barrier_arrive(unsigned* ctr) {
    asm volatile("red.release.gpu.global.add.u32 [%0], 1;" :: "l"(ctr) : "memory");
}
__device__ __forceinline__ void barrier_poll(unsigned* ctr, unsigned target) {
    unsigned v;
    do {
        asm volatile("ld.global.acquire.gpu.u32 %0, [%1];"
                     : "=r"(v) : "l"(ctr) : "memory");
        if (v < target) __nanosleep(16);
    } while (v < target);
}

// accumulate ITERS k-steps into acc (lane tile 8 rows x 4 batches)
template<int ITERS>
__device__ __forceinline__ void gemv_accum(
    const float* __restrict__ Wcol, const float* __restrict__ zcol,
    unsigned long long acc[4][4])
{
#pragma unroll 4
    for (int k = 0; k < ITERS; k++) {
        ulonglong2 wa = *(const ulonglong2*)(Wcol + k * 64);      // rows r0..r0+3
        ulonglong2 wb = *(const ulonglong2*)(Wcol + k * 64 + 4);  // rows r0+4..r0+7
        float4 z4 = *(const float4*)(zcol + k * 20);              // batches b0..b0+3
        unsigned long long zz[4];
        DUP2(zz[0], z4.x); DUP2(zz[1], z4.y);
        DUP2(zz[2], z4.z); DUP2(zz[3], z4.w);
#pragma unroll
        for (int j = 0; j < 4; j++) {
            FMA2(acc[0][j], wa.x, zz[j]);
            FMA2(acc[1][j], wa.y, zz[j]);
            FMA2(acc[2][j], wb.x, zz[j]);
            FMA2(acc[3][j], wb.y, zz[j]);
        }
    }
}

// fold lane bits 3,4 and store copy kq of a pbuf set (swizzled, lanes 0..7)
__device__ __forceinline__ void gemv_fold_store(
    unsigned long long acc[4][4], int kq, int r0, int b0, int lane,
    float* __restrict__ pset)
{
#pragma unroll
    for (int i = 0; i < 4; i++)
#pragma unroll
        for (int j = 0; j < 4; j++)
            acc[i][j] = bfly_add2(bfly_add2(acc[i][j], 8), 16);
    if (lane < 8) {
        float* pd = pset + kq * 1024;
#pragma unroll
        for (int j = 0; j < 4; j++) {
            const int b = b0 + j;
            float* col = pd + b * 64;
            const int sw = 2 * b;
#pragma unroll
            for (int i = 0; i < 4; i++)
                *(unsigned long long*)(col + ((r0 + 2 * i) ^ sw)) = acc[i][j];
        }
    }
}

// single-call gemv (L1/L2): contiguous chunk of KD/8 k-steps
template<int KD>
__device__ __forceinline__ void gemv_layer(
    const float* __restrict__ Wbase, const float* __restrict__ zbase,
    int kc, int kq, int r0, int b0, int lane, float* __restrict__ pset)
{
    constexpr int C = KD / 8;
    unsigned long long acc[4][4];
#pragma unroll
    for (int i = 0; i < 4; i++)
#pragma unroll
        for (int j = 0; j < 4; j++) acc[i][j] = 0ULL;
    gemv_accum<C>(Wbase + kc * (C * 64) + r0, zbase + kc * (C * 20) + b0, acc);
    gemv_fold_store(acc, kq, r0, b0, lane, pset);
}

// cell phase helper: gate sums from a pbuf set (2 copies), swizzled reads
__device__ __forceinline__ float4 gate_sums(const float* __restrict__ pset,
                                            int u, int b, float4 bL)
{
    const int sw = 2 * b;
    float gi = bL.x, gf = bL.y, go = bL.z, gg = bL.w;
#pragma unroll
    for (int c = 0; c < 2; c++) {
        const float* gb = pset + c * 1024 + b * 64;
        gi += gb[u ^ sw];
        gf += gb[(16 + u) ^ sw];
        go += gb[(32 + u) ^ sw];
        gg += gb[(48 + u) ^ sw];
    }
    return make_float4(gi, gf, go, gg);
}

__global__ void __launch_bounds__(256, 1) convlstm_kernel(
    const float* __restrict__ x,
    const float* __restrict__ W1, const float* __restrict__ b1,
    const float* __restrict__ W2, const float* __restrict__ b2,
    const float* __restrict__ W3, const float* __restrict__ b3,
    const float* __restrict__ h1i, const float* __restrict__ c1i,
    const float* __restrict__ h2i, const float* __restrict__ c2i,
    const float* __restrict__ h3i, const float* __restrict__ c3i,
    float* __restrict__ out)
{
    extern __shared__ float sm[];
    float* Wsm  = sm;
    float* zdf  = sm + ZD_OFF;
    float* pbuf = sm + PB_OFF;

    const int tid = threadIdx.x;
    const int gid = blockIdx.x & 7;    // gate-slice: hidden units [16*gid, +16)
    const int bg  = blockIdx.x >> 3;   // batch group: batches [16*bg, +16)
    const int bgb = bg << 4;
    unsigned* ctr = &g_ctr[bg * 32];

    // ---- Prologue: weight slices (center tap), plain [k][row64] ----
    for (int idx = tid; idx < 192 * 64; idx += 256) {
        int k = idx >> 6, r = idx & 63;
        int grow = ((r >> 4) << 7) | (gid << 4) | (r & 15);  // gate*128+gid*16+u
        Wsm[WOFF_L0 + idx] = W1[(size_t)grow * 576 + k * 3 + 1];
    }
    for (int idx = tid; idx < 256 * 64; idx += 256) {
        int k = idx >> 6, r = idx & 63;
        int grow = ((r >> 4) << 7) | (gid << 4) | (r & 15);
        Wsm[WOFF_L1 + idx] = W2[(size_t)grow * 768 + k * 3 + 1];
        Wsm[WOFF_L2 + idx] = W3[(size_t)grow * 768 + k * 3 + 1];
    }

    // ---- per-thread (u,b) registers: bias + c state ----
    const int u = tid >> 4, b = tid & 15;
    const int gub = (gid << 4) | u;
    float4 bL0 = make_float4(__ldg(&b1[gub]), __ldg(&b1[128 + gub]),
                             __ldg(&b1[256 + gub]), __ldg(&b1[384 + gub]));
    float4 bL1 = make_float4(__ldg(&b2[gub]), __ldg(&b2[128 + gub]),
                             __ldg(&b2[256 + gub]), __ldg(&b2[384 + gub]));
    float4 bL2 = make_float4(__ldg(&b3[gub]), __ldg(&b3[128 + gub]),
                             __ldg(&b3[256 + gub]), __ldg(&b3[384 + gub]));
    const int sidx = (bgb + b) * 128 + gub;
    float c0r = __ldg(&c1i[sidx]);
    float c1r = __ldg(&c2i[sidx]);
    float c2r = __ldg(&c3i[sidx]);

    // ---- publish initial h into both parities ----
    {
        float h0 = __ldg(&h1i[sidx]), h1v = __ldg(&h2i[sidx]), h2v = __ldg(&h3i[sidx]);
        int hb = gub * 256 + bgb + b;
#pragma unroll
        for (int par = 0; par < 2; par++) {
            g_hbuf[(0 * 2 + par) * 32768 + hb] = h0;
            g_hbuf[(1 * 2 + par) * 32768 + hb] = h1v;
            g_hbuf[(2 * 2 + par) * 32768 + hb] = h2v;
        }
    }
    // initial cross-CTA barrier
    unsigned target = 8;
    __syncthreads();
    if (tid == 0) {
        barrier_arrive(ctr);
        barrier_poll(ctr, target);
    }
    target += 8;
    __syncthreads();

    // ---- initial x(0) assembly (z rows 0..63) ----
    {
        const float* xb = x + (size_t)bgb * (T_STEPS * 64);
        int bb = tid >> 4, k4i = (tid & 15) << 2;
        float4 v = __ldg((const float4*)(xb + (size_t)bb * (T_STEPS * 64) + k4i));
        zdf[(k4i + 0) * 20 + bb] = v.x;
        zdf[(k4i + 1) * 20 + bb] = v.y;
        zdf[(k4i + 2) * 20 + bb] = v.z;
        zdf[(k4i + 3) * 20 + bb] = v.w;
    }
    __syncthreads();

    // GEMV warp/lane geometry (R13/R10)
    const int warp = tid >> 5, lane = tid & 31;
    const int kq = warp & 1;             // k-half (pbuf copy)
    const int rh = (warp >> 1) & 1;      // 32-row half
    const int bh = warp >> 2;            // 8-batch half
    const int ro = lane & 3;             // 8-row block within half
    const int bp = (lane >> 2) & 1;      // 4-batch within half
    const int kl = lane >> 3;            // in-lane k-chunk bits (folded)
    const int kc = kq * 4 + kl;          // k-chunk 0..7
    const int r0 = rh * 32 + ro * 8;     // rows r0..r0+7
    const int b0 = bh * 8 + bp * 4;      // batches b0..b0+3

    // h-assembly thread indexing
    const int aunit = tid >> 2;          // 0..63 (x2 with +64)
    const int ab4   = (tid & 3) << 2;

    // ======================= macro-step pipeline =======================
    for (int s = 0; s < T_STEPS + 2; s++) {
        const int pc = s & 1, pp = pc ^ 1;

        // ---- phase A: issue ALL h loads; gemv L0 seg1 (x rows); STS h0 ----
        float4 hv[6];
#pragma unroll
        for (int Lh = 0; Lh < 3; Lh++) {
            const float* src = &g_hbuf[(Lh * 2 + pp) * 32768 + bgb];
#pragma unroll
            for (int i = 0; i < 2; i++) {
                int unit = aunit + (i << 6);
                hv[Lh * 2 + i] = __ldcg((const float4*)&src[unit * 256 + ab4]);
            }
        }
        unsigned long long acc0[4][4];
#pragma unroll
        for (int i = 0; i < 4; i++)
#pragma unroll
            for (int j = 0; j < 4; j++) acc0[i][j] = 0ULL;
        if (s < T_STEPS)   // seg1: x rows kc*8..kc*8+8 (in smem since poll window)
            gemv_accum<8>(Wsm + WOFF_L0 + (kc * 8) * 64 + r0,
                          zdf + (kc * 8) * 20 + b0, acc0);
#pragma unroll
        for (int i = 0; i < 2; i++) {     // store h0 -> z rows 64..191
            int unit = aunit + (i << 6);
            *(float4*)&zdf[(64 + unit) * 20 + ab4] = hv[i];
        }
        __syncthreads();

        // ---- phase B: STS h1/h2 first; then gemv L0 seg2 -> set0 ----
#pragma unroll
        for (int Lh = 1; Lh <= 2; Lh++) {
#pragma unroll
            for (int i = 0; i < 2; i++) {
                int unit = aunit + (i << 6);
                *(float4*)&zdf[(64 + (Lh << 7) + unit) * 20 + ab4] = hv[Lh * 2 + i];
            }
        }
        if (s < T_STEPS) {
            gemv_accum<16>(Wsm + WOFF_L0 + (64 + kc * 16) * 64 + r0,
                           zdf + (64 + kc * 16) * 20 + b0, acc0);
            gemv_fold_store(acc0, kq, r0, b0, lane, pbuf);
        }
        __syncthreads();

        // ---- phase C: cell L0 (reads set0) first; then gemv L1 -> set1 ----
        if (s < T_STEPS) {
            float4 g = gate_sums(pbuf, u, b, bL0);
            float cn = sigm(g.y) * c0r + sigm(g.x) * tanh_f(g.w);
            float hn = sigm(g.z) * tanh_f(cn);
            c0r = cn;
            g_hbuf[(0 * 2 + pc) * 32768 + gub * 256 + bgb + b] = hn;
        }
        if (s >= 1 && s <= T_STEPS)
            gemv_layer<256>(Wsm + WOFF_L1, zdf + 64 * 20, kc, kq, r0, b0, lane,
                            pbuf + 2048);
        __syncthreads();

        // ---- phase D: cell L1 (reads set1) first; then gemv L2 -> set0 ----
        if (s >= 1 && s <= T_STEPS) {
            float4 g = gate_sums(pbuf + 2048, u, b, bL1);
            float cn = sigm(g.y) * c1r + sigm(g.x) * tanh_f(g.w);
            float hn = sigm(g.z) * tanh_f(cn);
            c1r = cn;
            g_hbuf[(1 * 2 + pc) * 32768 + gub * 256 + bgb + b] = hn;
        }
        if (s >= 2)
            gemv_layer<256>(Wsm + WOFF_L2, zdf + 192 * 20, kc, kq, r0, b0, lane,
                            pbuf);
        __syncthreads();

        // ---- phase E: cell L2 (reads set0) ----
        if (s >= 2) {
            float4 g = gate_sums(pbuf, u, b, bL2);
            float cn = sigm(g.y) * c2r + sigm(g.x) * tanh_f(g.w);
            float hn = sigm(g.z) * tanh_f(cn);
            c2r = cn;
            g_hbuf[(2 * 2 + pc) * 32768 + gub * 256 + bgb + b] = hn;
            if (s == T_STEPS + 1)
                out[(size_t)(bgb + b) * 128 + gub] = hn;
        }

        // ---- split cross-CTA barrier; x(s+1) assembly overlaps the poll ----
        __syncthreads();
        if (tid == 0)
            barrier_arrive(ctr);
        if (s + 1 < T_STEPS) {
            const float* xb = x + (size_t)bgb * (T_STEPS * 64) + (size_t)(s + 1) * 64;
            int bb = tid >> 4, k4i = (tid & 15) << 2;
            float4 v = __ldg((const float4*)(xb + (size_t)bb * (T_STEPS * 64) + k4i));
            zdf[(k4i + 0) * 20 + bb] = v.x;
            zdf[(k4i + 1) * 20 + bb] = v.y;
            zdf[(k4i + 2) * 20 + bb] = v.z;
            zdf[(k4i + 3) * 20 + bb] = v.w;
        }
        if (tid == 0)
            barrier_poll(ctr, target);
        target += 8;
        __syncthreads();
    }
}

extern "C" void kernel_launch(void* const* d_in, const int* in_sizes, int n_in,
                              void* d_out, int out_size) {
    (void)in_sizes; (void)n_in; (void)out_size;
    const float* x  = (const float*)d_in[0];
    const float* W1 = (const float*)d_in[1];
    const float* b1 = (const float*)d_in[2];
    const float* W2 = (const float*)d_in[3];
    const float* b2 = (const float*)d_in[4];
    const float* W3 = (const float*)d_in[5];
    const float* b3 = (const float*)d_in[6];
    const float* h1 = (const float*)d_in[7];
    const float* c1 = (const float*)d_in[8];
    const float* h2 = (const float*)d_in[9];
    const float* c2 = (const float*)d_in[10];
    const float* h3 = (const float*)d_in[11];
    const float* c3 = (const float*)d_in[12];
    float* out = (float*)d_out;

    cudaFuncSetAttribute(convlstm_kernel,
                         cudaFuncAttributeMaxDynamicSharedMemorySize, SMEM_BYTES);
    reset_ctr_kernel<<<1, 32>>>();
    convlstm_kernel<<<128, 256, SMEM_BYTES>>>(x, W1, b1, W2, b2, W3, b3,
                                              h1, c1, h2, c2, h3, c3, out);
}